// round 15
// baseline (speedup 1.0000x reference)
#include <cuda_runtime.h>
#include <cuda_fp16.h>
#include <math.h>
#include <cstdint>

#define N_NODES   50000
#define N_EDGES   800000
#define D_FEAT    128
#define D_HID     128
#define N_CLASSES 64
#define CAP       96

#define H2REF(u) (*(__half2*)&(u))

// ---------------- scratch (device globals; no allocation allowed) ----------
__device__ int    g_cnt[N_NODES];
__device__ float  g_dinv[N_NODES];
__device__ int    g_cols[(size_t)N_NODES * CAP];
__device__ __half g_z0s[(size_t)N_NODES * D_HID];
__device__ __half g_hh [(size_t)N_NODES * D_HID];
__device__ __half g_z1s[(size_t)N_NODES * N_CLASSES];
__device__ __half g_WT0[D_HID * D_FEAT];
__device__ __half g_WT1[N_CLASSES * D_HID];

// ---------------- helpers ----------------------------------------------------
__device__ __forceinline__ uint32_t smem_u32(const void* p) {
    uint32_t a;
    asm("{ .reg .u64 t; cvta.to.shared.u64 t, %1; cvt.u32.u64 %0, t; }" : "=r"(a) : "l"(p));
    return a;
}
__device__ __forceinline__ void ldsm_x4(uint32_t& r0, uint32_t& r1, uint32_t& r2, uint32_t& r3,
                                        uint32_t addr) {
    asm volatile("ldmatrix.sync.aligned.m8n8.x4.shared.b16 {%0,%1,%2,%3}, [%4];"
                 : "=r"(r0), "=r"(r1), "=r"(r2), "=r"(r3) : "r"(addr));
}
__device__ __forceinline__ void ldsm_x2(uint32_t& r0, uint32_t& r1, uint32_t addr) {
    asm volatile("ldmatrix.sync.aligned.m8n8.x2.shared.b16 {%0,%1}, [%2];"
                 : "=r"(r0), "=r"(r1) : "r"(addr));
}
__device__ __forceinline__ void mma16816(float* d, uint32_t a0, uint32_t a1, uint32_t a2,
                                         uint32_t a3, uint32_t b0, uint32_t b1) {
    asm volatile(
        "mma.sync.aligned.m16n8k16.row.col.f32.f16.f16.f32 "
        "{%0,%1,%2,%3}, {%4,%5,%6,%7}, {%8,%9}, {%0,%1,%2,%3};"
        : "+f"(d[0]), "+f"(d[1]), "+f"(d[2]), "+f"(d[3])
        : "r"(a0), "r"(a1), "r"(a2), "r"(a3), "r"(b0), "r"(b1));
}

// ---------------- adjacency build: 2 edges per thread ------------------------
__global__ void k_fill(const int* __restrict__ ei) {
    int e = (blockIdx.x * blockDim.x + threadIdx.x) * 2;
    if (e + 1 < N_EDGES) {
        int2 ss = *(const int2*)&ei[e];
        int2 dd = *(const int2*)&ei[N_EDGES + e];
        int p0 = atomicAdd(&g_cnt[ss.x], 1);
        if (p0 < CAP) g_cols[(size_t)ss.x * CAP + p0] = dd.x;
        int q0 = atomicAdd(&g_cnt[dd.x], 1);
        if (q0 < CAP) g_cols[(size_t)dd.x * CAP + q0] = ss.x;
        int p1 = atomicAdd(&g_cnt[ss.y], 1);
        if (p1 < CAP) g_cols[(size_t)ss.y * CAP + p1] = dd.y;
        int q1 = atomicAdd(&g_cnt[dd.y], 1);
        if (q1 < CAP) g_cols[(size_t)dd.y * CAP + q1] = ss.y;
    } else if (e < N_EDGES) {
        int s = ei[e];
        int d = ei[N_EDGES + e];
        int p = atomicAdd(&g_cnt[s], 1);
        if (p < CAP) g_cols[(size_t)s * CAP + p] = d;
        int q = atomicAdd(&g_cnt[d], 1);
        if (q < CAP) g_cols[(size_t)d * CAP + q] = s;
    }
}

// ---------------- dinv + W transpose + fp16 convert (fused) -----------------
__global__ void k_prep(const float* __restrict__ W0, const float* __restrict__ W1) {
    int i = blockIdx.x * blockDim.x + threadIdx.x;
    if (i < N_NODES) g_dinv[i] = rsqrtf((float)(g_cnt[i] + 1));
    if (i < D_HID * D_FEAT) {
        int n = i / D_FEAT, k = i % D_FEAT;
        g_WT0[i] = __float2half_rn(W0[(size_t)k * D_HID + n]);
    }
    if (i < N_CLASSES * D_HID) {
        int n = i / D_HID, k = i % D_HID;
        g_WT1[i] = __float2half_rn(W1[(size_t)k * N_CLASSES + n]);
    }
}

// ---------------- GEMM1 (HMMA, BM=128): z0s = dinv * (x @ W0) ---------------
__global__ void __launch_bounds__(256) gemm_mma(int M, const float* __restrict__ A,
                                                const __half* __restrict__ WT,
                                                __half* __restrict__ C) {
    constexpr int NOUT = 128;
    constexpr int PAD  = 136;
    constexpr int NT   = NOUT / 8;
    constexpr int A_SZ = 128 * PAD * 2;

    extern __shared__ char smem[];
    const uint32_t sbase = smem_u32(smem);
    const uint32_t OFF_A = 0, OFF_B = A_SZ;

    const int tid = threadIdx.x;
    const int w   = tid >> 5;
    const int l   = tid & 31;
    const int blockRow = blockIdx.x * 128;

#pragma unroll
    for (int p = 0; p < 16; p++) {
        const int row  = w + 8 * p;
        const int grow = blockRow + row;
        float4 v = make_float4(0.f, 0.f, 0.f, 0.f);
        if (grow < M) v = ((const float4*)A)[(size_t)grow * 32 + l];
        __half2 h0 = __floats2half2_rn(v.x, v.y);
        __half2 h1 = __floats2half2_rn(v.z, v.w);
        uint2 u;
        u.x = *(uint32_t*)&h0; u.y = *(uint32_t*)&h1;
        *(uint2*)((__half*)(smem + OFF_A) + row * PAD + l * 4) = u;
    }
    for (int i = tid; i < NOUT * 16; i += 256) {
        int row = i >> 4, c8 = (i & 15) * 8;
        uint4 u = *(const uint4*)&WT[(size_t)row * 128 + c8];
        *(uint4*)((__half*)(smem + OFF_B) + row * PAD + c8) = u;
    }
    __syncthreads();

    float acc[NT][4];
#pragma unroll
    for (int nt = 0; nt < NT; nt++)
#pragma unroll
        for (int j = 0; j < 4; j++) acc[nt][j] = 0.f;

    const uint32_t a_lane = sbase + OFF_A +
        (uint32_t)(((w * 16) + (l & 15)) * PAD + ((l & 16) ? 8 : 0)) * 2;
    const uint32_t b_lane = sbase + OFF_B +
        (uint32_t)((l & 7) * PAD + ((l >> 3) & 1) * 8) * 2;

#pragma unroll
    for (int kt = 0; kt < 8; kt++) {
        uint32_t a0, a1, a2, a3;
        ldsm_x4(a0, a1, a2, a3, a_lane + kt * 32);
#pragma unroll
        for (int nt = 0; nt < NT; nt++) {
            uint32_t b0, b1;
            ldsm_x2(b0, b1, b_lane + (uint32_t)(nt * 8 * PAD + kt * 16) * 2);
            mma16816(acc[nt], a0, a1, a2, a3, b0, b1);
        }
    }

    __syncthreads();
    __half* Cs = (__half*)(smem + OFF_A);
    {
        const int r0l = w * 16 + (l >> 2);
        const int r1l = r0l + 8;
        const int g0 = blockRow + r0l, g1r = blockRow + r1l;
        const float s0 = (g0 < M) ? g_dinv[g0] : 0.f;
        const float s1 = (g1r < M) ? g_dinv[g1r] : 0.f;
        const int col = (l & 3) * 2;
#pragma unroll
        for (int nt = 0; nt < NT; nt++) {
            __half2 h0 = __floats2half2_rn(s0 * acc[nt][0], s0 * acc[nt][1]);
            __half2 h1 = __floats2half2_rn(s1 * acc[nt][2], s1 * acc[nt][3]);
            *(__half2*)&Cs[r0l * PAD + nt * 8 + col] = h0;
            *(__half2*)&Cs[r1l * PAD + nt * 8 + col] = h1;
        }
    }
    __syncthreads();
#pragma unroll
    for (int p = 0; p < 8; p++) {
        const int rl   = w * 16 + p * 2 + (l >> 4);
        const int grow = blockRow + rl;
        if (grow < M) {
            uint4 v = *(uint4*)&Cs[rl * PAD + (l & 15) * 8];
            *(uint4*)&C[(size_t)grow * NOUT + (l & 15) * 8] = v;
        }
    }
}

// ---------------- GEMM2 (HMMA, BM=128): z1s = dinv * (h @ W1), A fp16 --------
__global__ void __launch_bounds__(256) gemm_mma_h(int M, const __half* __restrict__ A,
                                                  const __half* __restrict__ WT,
                                                  __half* __restrict__ C) {
    constexpr int NOUT = 64;
    constexpr int PAD  = 136;
    constexpr int NT   = NOUT / 8;
    constexpr int A_SZ = 128 * PAD * 2;

    extern __shared__ char smem[];
    const uint32_t sbase = smem_u32(smem);
    const uint32_t OFF_A = 0, OFF_B = A_SZ;

    const int tid = threadIdx.x;
    const int w   = tid >> 5;
    const int l   = tid & 31;
    const int blockRow = blockIdx.x * 128;

#pragma unroll
    for (int p = 0; p < 16; p++) {
        const int row  = w + 8 * p;
        const int grow = blockRow + row;
        uint2 u = make_uint2(0, 0);
        if (grow < M) u = ((const uint2*)A)[(size_t)grow * 32 + l];
        *(uint2*)((__half*)(smem + OFF_A) + row * PAD + l * 4) = u;
    }
    for (int i = tid; i < NOUT * 16; i += 256) {
        int row = i >> 4, c8 = (i & 15) * 8;
        uint4 u = *(const uint4*)&WT[(size_t)row * 128 + c8];
        *(uint4*)((__half*)(smem + OFF_B) + row * PAD + c8) = u;
    }
    __syncthreads();

    float acc[NT][4];
#pragma unroll
    for (int nt = 0; nt < NT; nt++)
#pragma unroll
        for (int j = 0; j < 4; j++) acc[nt][j] = 0.f;

    const uint32_t a_lane = sbase + OFF_A +
        (uint32_t)(((w * 16) + (l & 15)) * PAD + ((l & 16) ? 8 : 0)) * 2;
    const uint32_t b_lane = sbase + OFF_B +
        (uint32_t)((l & 7) * PAD + ((l >> 3) & 1) * 8) * 2;

#pragma unroll
    for (int kt = 0; kt < 8; kt++) {
        uint32_t a0, a1, a2, a3;
        ldsm_x4(a0, a1, a2, a3, a_lane + kt * 32);
#pragma unroll
        for (int nt = 0; nt < NT; nt++) {
            uint32_t b0, b1;
            ldsm_x2(b0, b1, b_lane + (uint32_t)(nt * 8 * PAD + kt * 16) * 2);
            mma16816(acc[nt], a0, a1, a2, a3, b0, b1);
        }
    }

    __syncthreads();
    __half* Cs = (__half*)(smem + OFF_A);
    {
        const int r0l = w * 16 + (l >> 2);
        const int r1l = r0l + 8;
        const int g0 = blockRow + r0l, g1r = blockRow + r1l;
        const float s0 = (g0 < M) ? g_dinv[g0] : 0.f;
        const float s1 = (g1r < M) ? g_dinv[g1r] : 0.f;
        const int col = (l & 3) * 2;
#pragma unroll
        for (int nt = 0; nt < NT; nt++) {
            __half2 h0 = __floats2half2_rn(s0 * acc[nt][0], s0 * acc[nt][1]);
            __half2 h1 = __floats2half2_rn(s1 * acc[nt][2], s1 * acc[nt][3]);
            *(__half2*)&Cs[r0l * PAD + nt * 8 + col] = h0;
            *(__half2*)&Cs[r1l * PAD + nt * 8 + col] = h1;
        }
    }
    __syncthreads();
#pragma unroll
    for (int p = 0; p < 4; p++) {
        const int rl   = w * 16 + p * 4 + (l >> 3);
        const int grow = blockRow + rl;
        if (grow < M) {
            uint4 v = *(uint4*)&Cs[rl * PAD + (l & 7) * 8];
            *(uint4*)&C[(size_t)grow * NOUT + (l & 7) * 8] = v;
        }
    }
}

// ---------------- SpMM1: h = relu(dinv * (gather z0s)) -> fp16 (512 thr) ----
__global__ void __launch_bounds__(512) spmm_h16(const __half* __restrict__ Hs,
                                                __half* __restrict__ Hout) {
    constexpr int F = D_HID;
    const int lane = threadIdx.x & 31;
    const int warp = threadIdx.x >> 5;
    const int row  = blockIdx.x * 16 + warp;
    if (row >= N_NODES) return;

    const float di = g_dinv[row];
    const __half* __restrict__ base = Hs + (size_t)lane * 4;

    float a0, a1, a2, a3;
    {
        uint2 u = *(const uint2*)(base + (size_t)row * F);
        float2 f01 = __half22float2(H2REF(u.x));
        float2 f23 = __half22float2(H2REF(u.y));
        a0 = f01.x; a1 = f01.y; a2 = f23.x; a3 = f23.y;
    }

    int n = g_cnt[row];
    n = (n < CAP) ? n : CAP;
    const int* __restrict__ cp = g_cols + (size_t)row * CAP;

    int j = 0;
    for (; j + 15 < n; j += 16) {
        int4 ia = *(const int4*)&cp[j];
        int4 ib = *(const int4*)&cp[j + 4];
        int4 ic = *(const int4*)&cp[j + 8];
        int4 id = *(const int4*)&cp[j + 12];
        uint2 u0 = *(const uint2*)(base + (size_t)ia.x * F);
        uint2 u1 = *(const uint2*)(base + (size_t)ia.y * F);
        uint2 u2 = *(const uint2*)(base + (size_t)ia.z * F);
        uint2 u3 = *(const uint2*)(base + (size_t)ia.w * F);
        uint2 u4 = *(const uint2*)(base + (size_t)ib.x * F);
        uint2 u5 = *(const uint2*)(base + (size_t)ib.y * F);
        uint2 u6 = *(const uint2*)(base + (size_t)ib.z * F);
        uint2 u7 = *(const uint2*)(base + (size_t)ib.w * F);
        uint2 u8 = *(const uint2*)(base + (size_t)ic.x * F);
        uint2 u9 = *(const uint2*)(base + (size_t)ic.y * F);
        uint2 uA = *(const uint2*)(base + (size_t)ic.z * F);
        uint2 uB = *(const uint2*)(base + (size_t)ic.w * F);
        uint2 uC = *(const uint2*)(base + (size_t)id.x * F);
        uint2 uD = *(const uint2*)(base + (size_t)id.y * F);
        uint2 uE = *(const uint2*)(base + (size_t)id.z * F);
        uint2 uF = *(const uint2*)(base + (size_t)id.w * F);
        __half2 x0 = __hadd2(H2REF(u0.x), H2REF(u1.x));
        __half2 x1 = __hadd2(H2REF(u2.x), H2REF(u3.x));
        __half2 x2 = __hadd2(H2REF(u4.x), H2REF(u5.x));
        __half2 x3 = __hadd2(H2REF(u6.x), H2REF(u7.x));
        __half2 x4 = __hadd2(H2REF(u8.x), H2REF(u9.x));
        __half2 x5 = __hadd2(H2REF(uA.x), H2REF(uB.x));
        __half2 x6 = __hadd2(H2REF(uC.x), H2REF(uD.x));
        __half2 x7 = __hadd2(H2REF(uE.x), H2REF(uF.x));
        x0 = __hadd2(x0, x1); x2 = __hadd2(x2, x3);
        x4 = __hadd2(x4, x5); x6 = __hadd2(x6, x7);
        x0 = __hadd2(x0, x2); x4 = __hadd2(x4, x6);
        x0 = __hadd2(x0, x4);
        __half2 y0 = __hadd2(H2REF(u0.y), H2REF(u1.y));
        __half2 y1 = __hadd2(H2REF(u2.y), H2REF(u3.y));
        __half2 y2 = __hadd2(H2REF(u4.y), H2REF(u5.y));
        __half2 y3 = __hadd2(H2REF(u6.y), H2REF(u7.y));
        __half2 y4 = __hadd2(H2REF(u8.y), H2REF(u9.y));
        __half2 y5 = __hadd2(H2REF(uA.y), H2REF(uB.y));
        __half2 y6 = __hadd2(H2REF(uC.y), H2REF(uD.y));
        __half2 y7 = __hadd2(H2REF(uE.y), H2REF(uF.y));
        y0 = __hadd2(y0, y1); y2 = __hadd2(y2, y3);
        y4 = __hadd2(y4, y5); y6 = __hadd2(y6, y7);
        y0 = __hadd2(y0, y2); y4 = __hadd2(y4, y6);
        y0 = __hadd2(y0, y4);
        float2 fx = __half22float2(x0);
        float2 fy = __half22float2(y0);
        a0 += fx.x; a1 += fx.y; a2 += fy.x; a3 += fy.y;
    }
    for (; j + 7 < n; j += 8) {
        int4 ia = *(const int4*)&cp[j];
        int4 ib = *(const int4*)&cp[j + 4];
        uint2 u0 = *(const uint2*)(base + (size_t)ia.x * F);
        uint2 u1 = *(const uint2*)(base + (size_t)ia.y * F);
        uint2 u2 = *(const uint2*)(base + (size_t)ia.z * F);
        uint2 u3 = *(const uint2*)(base + (size_t)ia.w * F);
        uint2 u4 = *(const uint2*)(base + (size_t)ib.x * F);
        uint2 u5 = *(const uint2*)(base + (size_t)ib.y * F);
        uint2 u6 = *(const uint2*)(base + (size_t)ib.z * F);
        uint2 u7 = *(const uint2*)(base + (size_t)ib.w * F);
        __half2 x0 = __hadd2(H2REF(u0.x), H2REF(u1.x));
        __half2 x1 = __hadd2(H2REF(u2.x), H2REF(u3.x));
        __half2 x2 = __hadd2(H2REF(u4.x), H2REF(u5.x));
        __half2 x3 = __hadd2(H2REF(u6.x), H2REF(u7.x));
        x0 = __hadd2(x0, x1); x2 = __hadd2(x2, x3);
        x0 = __hadd2(x0, x2);
        __half2 y0 = __hadd2(H2REF(u0.y), H2REF(u1.y));
        __half2 y1 = __hadd2(H2REF(u2.y), H2REF(u3.y));
        __half2 y2 = __hadd2(H2REF(u4.y), H2REF(u5.y));
        __half2 y3 = __hadd2(H2REF(u6.y), H2REF(u7.y));
        y0 = __hadd2(y0, y1); y2 = __hadd2(y2, y3);
        y0 = __hadd2(y0, y2);
        float2 fx = __half22float2(x0);
        float2 fy = __half22float2(y0);
        a0 += fx.x; a1 += fx.y; a2 += fy.x; a3 += fy.y;
    }
    for (; j < n; j++) {
        int c = __ldg(&cp[j]);
        uint2 u = *(const uint2*)(base + (size_t)c * F);
        float2 f;
        f = __half22float2(H2REF(u.x)); a0 += f.x; a1 += f.y;
        f = __half22float2(H2REF(u.y)); a2 += f.x; a3 += f.y;
    }

    a0 = fmaxf(a0 * di, 0.f); a1 = fmaxf(a1 * di, 0.f);
    a2 = fmaxf(a2 * di, 0.f); a3 = fmaxf(a3 * di, 0.f);
    __half2 h0 = __floats2half2_rn(a0, a1);
    __half2 h1 = __floats2half2_rn(a2, a3);
    uint2 u;
    u.x = *(uint32_t*)&h0; u.y = *(uint32_t*)&h1;
    *(uint2*)(Hout + (size_t)row * F + (size_t)lane * 4) = u;
}

// ---------------- SpMM2: out = dinv * gather(z1s) -> fp32 (512 thr) ---------
__global__ void __launch_bounds__(512) spmm_out(const __half* __restrict__ Hs,
                                                float* __restrict__ Hout) {
    constexpr int F = N_CLASSES;
    const int lane = threadIdx.x & 31;
    const int warp = threadIdx.x >> 5;
    const int row  = blockIdx.x * 16 + warp;
    if (row >= N_NODES) return;

    const float di = g_dinv[row];
    const __half* __restrict__ base = Hs + (size_t)lane * 2;

    float a0, a1;
    {
        unsigned int u = *(const unsigned int*)(base + (size_t)row * F);
        float2 f = __half22float2(H2REF(u));
        a0 = f.x; a1 = f.y;
    }
    int n = g_cnt[row];
    n = (n < CAP) ? n : CAP;
    const int* __restrict__ cp = g_cols + (size_t)row * CAP;

    int j = 0;
    for (; j + 15 < n; j += 16) {
        int4 ia = *(const int4*)&cp[j];
        int4 ib = *(const int4*)&cp[j + 4];
        int4 ic = *(const int4*)&cp[j + 8];
        int4 id = *(const int4*)&cp[j + 12];
        unsigned int u0 = *(const unsigned int*)(base + (size_t)ia.x * F);
        unsigned int u1 = *(const unsigned int*)(base + (size_t)ia.y * F);
        unsigned int u2 = *(const unsigned int*)(base + (size_t)ia.z * F);
        unsigned int u3 = *(const unsigned int*)(base + (size_t)ia.w * F);
        unsigned int u4 = *(const unsigned int*)(base + (size_t)ib.x * F);
        unsigned int u5 = *(const unsigned int*)(base + (size_t)ib.y * F);
        unsigned int u6 = *(const unsigned int*)(base + (size_t)ib.z * F);
        unsigned int u7 = *(const unsigned int*)(base + (size_t)ib.w * F);
        unsigned int u8 = *(const unsigned int*)(base + (size_t)ic.x * F);
        unsigned int u9 = *(const unsigned int*)(base + (size_t)ic.y * F);
        unsigned int uA = *(const unsigned int*)(base + (size_t)ic.z * F);
        unsigned int uB = *(const unsigned int*)(base + (size_t)ic.w * F);
        unsigned int uC = *(const unsigned int*)(base + (size_t)id.x * F);
        unsigned int uD = *(const unsigned int*)(base + (size_t)id.y * F);
        unsigned int uE = *(const unsigned int*)(base + (size_t)id.z * F);
        unsigned int uF = *(const unsigned int*)(base + (size_t)id.w * F);
        __half2 s0 = __hadd2(H2REF(u0), H2REF(u1));
        __half2 s1 = __hadd2(H2REF(u2), H2REF(u3));
        __half2 s2 = __hadd2(H2REF(u4), H2REF(u5));
        __half2 s3 = __hadd2(H2REF(u6), H2REF(u7));
        __half2 s4 = __hadd2(H2REF(u8), H2REF(u9));
        __half2 s5 = __hadd2(H2REF(uA), H2REF(uB));
        __half2 s6 = __hadd2(H2REF(uC), H2REF(uD));
        __half2 s7 = __hadd2(H2REF(uE), H2REF(uF));
        s0 = __hadd2(s0, s1); s2 = __hadd2(s2, s3);
        s4 = __hadd2(s4, s5); s6 = __hadd2(s6, s7);
        s0 = __hadd2(s0, s2); s4 = __hadd2(s4, s6);
        s0 = __hadd2(s0, s4);
        float2 f = __half22float2(s0);
        a0 += f.x; a1 += f.y;
    }
    for (; j + 7 < n; j += 8) {
        int4 ia = *(const int4*)&cp[j];
        int4 ib = *(const int4*)&cp[j + 4];
        unsigned int u0 = *(const unsigned int*)(base + (size_t)ia.x * F);
        unsigned int u1 = *(const unsigned int*)(base + (size_t)ia.y * F);
        unsigned int u2 = *(const unsigned int*)(base + (size_t)ia.z * F);
        unsigned int u3 = *(const unsigned int*)(base + (size_t)ia.w * F);
        unsigned int u4 = *(const unsigned int*)(base + (size_t)ib.x * F);
        unsigned int u5 = *(const unsigned int*)(base + (size_t)ib.y * F);
        unsigned int u6 = *(const unsigned int*)(base + (size_t)ib.z * F);
        unsigned int u7 = *(const unsigned int*)(base + (size_t)ib.w * F);
        __half2 s0 = __hadd2(H2REF(u0), H2REF(u1));
        __half2 s1 = __hadd2(H2REF(u2), H2REF(u3));
        __half2 s2 = __hadd2(H2REF(u4), H2REF(u5));
        __half2 s3 = __hadd2(H2REF(u6), H2REF(u7));
        s0 = __hadd2(s0, s1); s2 = __hadd2(s2, s3);
        s0 = __hadd2(s0, s2);
        float2 f = __half22float2(s0);
        a0 += f.x; a1 += f.y;
    }
    for (; j < n; j++) {
        int c = __ldg(&cp[j]);
        unsigned int u = *(const unsigned int*)(base + (size_t)c * F);
        float2 f = __half22float2(H2REF(u));
        a0 += f.x; a1 += f.y;
    }

    a0 *= di; a1 *= di;
    *(float2*)&Hout[(size_t)row * F + (size_t)lane * 2] = make_float2(a0, a1);
}

// ---------------- launch ----------------------------------------------------
extern "C" void kernel_launch(void* const* d_in, const int* in_sizes, int n_in,
                              void* d_out, int out_size) {
    const float* x  = (const float*)d_in[0];
    const float* W0 = (const float*)d_in[1];
    const float* W1 = (const float*)d_in[2];
    const int*   ei = (const int*)d_in[3];
    float* out = (float*)d_out;

    __half* z0sp; __half* hhp; __half* z1sp; int* cntp; __half* wt0p; __half* wt1p;
    cudaGetSymbolAddress((void**)&z0sp, g_z0s);
    cudaGetSymbolAddress((void**)&hhp,  g_hh);
    cudaGetSymbolAddress((void**)&z1sp, g_z1s);
    cudaGetSymbolAddress((void**)&cntp, g_cnt);
    cudaGetSymbolAddress((void**)&wt0p, g_WT0);
    cudaGetSymbolAddress((void**)&wt1p, g_WT1);

    const int SMEM1 = 128 * 136 * 2 + 128 * 136 * 2;   // 69632
    const int SMEM2 = 128 * 136 * 2 + 64 * 136 * 2;    // 52224
    cudaFuncSetAttribute(gemm_mma,   cudaFuncAttributeMaxDynamicSharedMemorySize, SMEM1);
    cudaFuncSetAttribute(gemm_mma_h, cudaFuncAttributeMaxDynamicSharedMemorySize, SMEM2);

    const int T = 256;
    const int NBLK = (N_NODES + 127) / 128;   // 391

    cudaMemsetAsync(cntp, 0, N_NODES * sizeof(int));
    k_fill<<<((N_EDGES + 1) / 2 + T - 1) / T, T>>>(ei);
    k_prep<<<(N_NODES + T - 1) / T, T>>>(W0, W1);

    // z0s = dinv * (x @ W0) -> fp16
    gemm_mma<<<NBLK, 256, SMEM1>>>(N_NODES, x, wt0p, z0sp);

    // h = relu(dinv * gather(z0s)) -> fp16
    spmm_h16<<<(N_NODES + 15) / 16, 512>>>(z0sp, hhp);

    // z1s = dinv * (h @ W1) -> fp16
    gemm_mma_h<<<NBLK, 256, SMEM2>>>(N_NODES, hhp, wt1p, z1sp);

    // out = dinv * gather(z1s) -> fp32
    spmm_out<<<(N_NODES + 15) / 16, 512>>>(z1sp, out);
}

// round 16
// speedup vs baseline: 1.0378x; 1.0378x over previous
#include <cuda_runtime.h>
#include <cuda_fp16.h>
#include <math.h>
#include <cstdint>

#define N_NODES   50000
#define N_EDGES   800000
#define D_FEAT    128
#define D_HID     128
#define N_CLASSES 64
#define CAP       96

#define H2REF(u) (*(__half2*)&(u))

// ---------------- scratch (device globals; no allocation allowed) ----------
__device__ int    g_cnt[N_NODES];
__device__ float  g_dinv[N_NODES];
__device__ int    g_cols[(size_t)N_NODES * CAP];
__device__ __half g_z0s[(size_t)N_NODES * D_HID];
__device__ __half g_hh [(size_t)N_NODES * D_HID];
__device__ __half g_z1s[(size_t)N_NODES * N_CLASSES];
__device__ __half g_WT0[D_HID * D_FEAT];
__device__ __half g_WT1[N_CLASSES * D_HID];

// ---------------- helpers ----------------------------------------------------
__device__ __forceinline__ uint32_t smem_u32(const void* p) {
    uint32_t a;
    asm("{ .reg .u64 t; cvta.to.shared.u64 t, %1; cvt.u32.u64 %0, t; }" : "=r"(a) : "l"(p));
    return a;
}
__device__ __forceinline__ void ldsm_x4(uint32_t& r0, uint32_t& r1, uint32_t& r2, uint32_t& r3,
                                        uint32_t addr) {
    asm volatile("ldmatrix.sync.aligned.m8n8.x4.shared.b16 {%0,%1,%2,%3}, [%4];"
                 : "=r"(r0), "=r"(r1), "=r"(r2), "=r"(r3) : "r"(addr));
}
__device__ __forceinline__ void ldsm_x2(uint32_t& r0, uint32_t& r1, uint32_t addr) {
    asm volatile("ldmatrix.sync.aligned.m8n8.x2.shared.b16 {%0,%1}, [%2];"
                 : "=r"(r0), "=r"(r1) : "r"(addr));
}
__device__ __forceinline__ void mma16816(float* d, uint32_t a0, uint32_t a1, uint32_t a2,
                                         uint32_t a3, uint32_t b0, uint32_t b1) {
    asm volatile(
        "mma.sync.aligned.m16n8k16.row.col.f32.f16.f16.f32 "
        "{%0,%1,%2,%3}, {%4,%5,%6,%7}, {%8,%9}, {%0,%1,%2,%3};"
        : "+f"(d[0]), "+f"(d[1]), "+f"(d[2]), "+f"(d[3])
        : "r"(a0), "r"(a1), "r"(a2), "r"(a3), "r"(b0), "r"(b1));
}

// ---------------- adjacency build: 2 edges per thread ------------------------
__global__ void k_fill(const int* __restrict__ ei) {
    int e = (blockIdx.x * blockDim.x + threadIdx.x) * 2;
    if (e + 1 < N_EDGES) {
        int2 ss = *(const int2*)&ei[e];
        int2 dd = *(const int2*)&ei[N_EDGES + e];
        int p0 = atomicAdd(&g_cnt[ss.x], 1);
        if (p0 < CAP) g_cols[(size_t)ss.x * CAP + p0] = dd.x;
        int q0 = atomicAdd(&g_cnt[dd.x], 1);
        if (q0 < CAP) g_cols[(size_t)dd.x * CAP + q0] = ss.x;
        int p1 = atomicAdd(&g_cnt[ss.y], 1);
        if (p1 < CAP) g_cols[(size_t)ss.y * CAP + p1] = dd.y;
        int q1 = atomicAdd(&g_cnt[dd.y], 1);
        if (q1 < CAP) g_cols[(size_t)dd.y * CAP + q1] = ss.y;
    } else if (e < N_EDGES) {
        int s = ei[e];
        int d = ei[N_EDGES + e];
        int p = atomicAdd(&g_cnt[s], 1);
        if (p < CAP) g_cols[(size_t)s * CAP + p] = d;
        int q = atomicAdd(&g_cnt[d], 1);
        if (q < CAP) g_cols[(size_t)d * CAP + q] = s;
    }
}

// ---------------- dinv + W transpose + fp16 convert (fused) -----------------
__global__ void k_prep(const float* __restrict__ W0, const float* __restrict__ W1) {
    int i = blockIdx.x * blockDim.x + threadIdx.x;
    if (i < N_NODES) g_dinv[i] = rsqrtf((float)(g_cnt[i] + 1));
    if (i < D_HID * D_FEAT) {
        int n = i / D_FEAT, k = i % D_FEAT;
        g_WT0[i] = __float2half_rn(W0[(size_t)k * D_HID + n]);
    }
    if (i < N_CLASSES * D_HID) {
        int n = i / D_HID, k = i % D_HID;
        g_WT1[i] = __float2half_rn(W1[(size_t)k * N_CLASSES + n]);
    }
}

// ---------------- GEMM1 (HMMA, BM=128): z0s = dinv * (x @ W0) ---------------
__global__ void __launch_bounds__(256) gemm_mma(int M, const float* __restrict__ A,
                                                const __half* __restrict__ WT,
                                                __half* __restrict__ C) {
    constexpr int NOUT = 128;
    constexpr int PAD  = 136;
    constexpr int NT   = NOUT / 8;
    constexpr int A_SZ = 128 * PAD * 2;

    extern __shared__ char smem[];
    const uint32_t sbase = smem_u32(smem);
    const uint32_t OFF_A = 0, OFF_B = A_SZ;

    const int tid = threadIdx.x;
    const int w   = tid >> 5;
    const int l   = tid & 31;
    const int blockRow = blockIdx.x * 128;

#pragma unroll
    for (int p = 0; p < 16; p++) {
        const int row  = w + 8 * p;
        const int grow = blockRow + row;
        float4 v = make_float4(0.f, 0.f, 0.f, 0.f);
        if (grow < M) v = ((const float4*)A)[(size_t)grow * 32 + l];
        __half2 h0 = __floats2half2_rn(v.x, v.y);
        __half2 h1 = __floats2half2_rn(v.z, v.w);
        uint2 u;
        u.x = *(uint32_t*)&h0; u.y = *(uint32_t*)&h1;
        *(uint2*)((__half*)(smem + OFF_A) + row * PAD + l * 4) = u;
    }
    for (int i = tid; i < NOUT * 16; i += 256) {
        int row = i >> 4, c8 = (i & 15) * 8;
        uint4 u = *(const uint4*)&WT[(size_t)row * 128 + c8];
        *(uint4*)((__half*)(smem + OFF_B) + row * PAD + c8) = u;
    }
    __syncthreads();

    float acc[NT][4];
#pragma unroll
    for (int nt = 0; nt < NT; nt++)
#pragma unroll
        for (int j = 0; j < 4; j++) acc[nt][j] = 0.f;

    const uint32_t a_lane = sbase + OFF_A +
        (uint32_t)(((w * 16) + (l & 15)) * PAD + ((l & 16) ? 8 : 0)) * 2;
    const uint32_t b_lane = sbase + OFF_B +
        (uint32_t)((l & 7) * PAD + ((l >> 3) & 1) * 8) * 2;

#pragma unroll
    for (int kt = 0; kt < 8; kt++) {
        uint32_t a0, a1, a2, a3;
        ldsm_x4(a0, a1, a2, a3, a_lane + kt * 32);
#pragma unroll
        for (int nt = 0; nt < NT; nt++) {
            uint32_t b0, b1;
            ldsm_x2(b0, b1, b_lane + (uint32_t)(nt * 8 * PAD + kt * 16) * 2);
            mma16816(acc[nt], a0, a1, a2, a3, b0, b1);
        }
    }

    __syncthreads();
    __half* Cs = (__half*)(smem + OFF_A);
    {
        const int r0l = w * 16 + (l >> 2);
        const int r1l = r0l + 8;
        const int g0 = blockRow + r0l, g1r = blockRow + r1l;
        const float s0 = (g0 < M) ? g_dinv[g0] : 0.f;
        const float s1 = (g1r < M) ? g_dinv[g1r] : 0.f;
        const int col = (l & 3) * 2;
#pragma unroll
        for (int nt = 0; nt < NT; nt++) {
            __half2 h0 = __floats2half2_rn(s0 * acc[nt][0], s0 * acc[nt][1]);
            __half2 h1 = __floats2half2_rn(s1 * acc[nt][2], s1 * acc[nt][3]);
            *(__half2*)&Cs[r0l * PAD + nt * 8 + col] = h0;
            *(__half2*)&Cs[r1l * PAD + nt * 8 + col] = h1;
        }
    }
    __syncthreads();
#pragma unroll
    for (int p = 0; p < 8; p++) {
        const int rl   = w * 16 + p * 2 + (l >> 4);
        const int grow = blockRow + rl;
        if (grow < M) {
            uint4 v = *(uint4*)&Cs[rl * PAD + (l & 15) * 8];
            *(uint4*)&C[(size_t)grow * NOUT + (l & 15) * 8] = v;
        }
    }
}

// ---------------- GEMM2 (HMMA, BM=128): z1s = dinv * (h @ W1), A fp16 --------
__global__ void __launch_bounds__(256) gemm_mma_h(int M, const __half* __restrict__ A,
                                                  const __half* __restrict__ WT,
                                                  __half* __restrict__ C) {
    constexpr int NOUT = 64;
    constexpr int PAD  = 136;
    constexpr int NT   = NOUT / 8;
    constexpr int A_SZ = 128 * PAD * 2;

    extern __shared__ char smem[];
    const uint32_t sbase = smem_u32(smem);
    const uint32_t OFF_A = 0, OFF_B = A_SZ;

    const int tid = threadIdx.x;
    const int w   = tid >> 5;
    const int l   = tid & 31;
    const int blockRow = blockIdx.x * 128;

#pragma unroll
    for (int p = 0; p < 16; p++) {
        const int row  = w + 8 * p;
        const int grow = blockRow + row;
        uint2 u = make_uint2(0, 0);
        if (grow < M) u = ((const uint2*)A)[(size_t)grow * 32 + l];
        *(uint2*)((__half*)(smem + OFF_A) + row * PAD + l * 4) = u;
    }
    for (int i = tid; i < NOUT * 16; i += 256) {
        int row = i >> 4, c8 = (i & 15) * 8;
        uint4 u = *(const uint4*)&WT[(size_t)row * 128 + c8];
        *(uint4*)((__half*)(smem + OFF_B) + row * PAD + c8) = u;
    }
    __syncthreads();

    float acc[NT][4];
#pragma unroll
    for (int nt = 0; nt < NT; nt++)
#pragma unroll
        for (int j = 0; j < 4; j++) acc[nt][j] = 0.f;

    const uint32_t a_lane = sbase + OFF_A +
        (uint32_t)(((w * 16) + (l & 15)) * PAD + ((l & 16) ? 8 : 0)) * 2;
    const uint32_t b_lane = sbase + OFF_B +
        (uint32_t)((l & 7) * PAD + ((l >> 3) & 1) * 8) * 2;

#pragma unroll
    for (int kt = 0; kt < 8; kt++) {
        uint32_t a0, a1, a2, a3;
        ldsm_x4(a0, a1, a2, a3, a_lane + kt * 32);
#pragma unroll
        for (int nt = 0; nt < NT; nt++) {
            uint32_t b0, b1;
            ldsm_x2(b0, b1, b_lane + (uint32_t)(nt * 8 * PAD + kt * 16) * 2);
            mma16816(acc[nt], a0, a1, a2, a3, b0, b1);
        }
    }

    __syncthreads();
    __half* Cs = (__half*)(smem + OFF_A);
    {
        const int r0l = w * 16 + (l >> 2);
        const int r1l = r0l + 8;
        const int g0 = blockRow + r0l, g1r = blockRow + r1l;
        const float s0 = (g0 < M) ? g_dinv[g0] : 0.f;
        const float s1 = (g1r < M) ? g_dinv[g1r] : 0.f;
        const int col = (l & 3) * 2;
#pragma unroll
        for (int nt = 0; nt < NT; nt++) {
            __half2 h0 = __floats2half2_rn(s0 * acc[nt][0], s0 * acc[nt][1]);
            __half2 h1 = __floats2half2_rn(s1 * acc[nt][2], s1 * acc[nt][3]);
            *(__half2*)&Cs[r0l * PAD + nt * 8 + col] = h0;
            *(__half2*)&Cs[r1l * PAD + nt * 8 + col] = h1;
        }
    }
    __syncthreads();
#pragma unroll
    for (int p = 0; p < 4; p++) {
        const int rl   = w * 16 + p * 4 + (l >> 3);
        const int grow = blockRow + rl;
        if (grow < M) {
            uint4 v = *(uint4*)&Cs[rl * PAD + (l & 7) * 8];
            *(uint4*)&C[(size_t)grow * NOUT + (l & 7) * 8] = v;
        }
    }
}

// ---------------- SpMM1: h = relu(dinv * (gather z0s)) -> fp16 --------------
__global__ void __launch_bounds__(256) spmm_h16(const __half* __restrict__ Hs,
                                                __half* __restrict__ Hout) {
    constexpr int F = D_HID;
    const int lane = threadIdx.x & 31;
    const int warp = threadIdx.x >> 5;
    const int row  = blockIdx.x * 8 + warp;
    if (row >= N_NODES) return;

    const float di = g_dinv[row];
    const __half* __restrict__ base = Hs + (size_t)lane * 4;

    float a0, a1, a2, a3;
    {
        uint2 u = *(const uint2*)(base + (size_t)row * F);
        float2 f01 = __half22float2(H2REF(u.x));
        float2 f23 = __half22float2(H2REF(u.y));
        a0 = f01.x; a1 = f01.y; a2 = f23.x; a3 = f23.y;
    }

    int n = g_cnt[row];
    n = (n < CAP) ? n : CAP;
    const int* __restrict__ cp = g_cols + (size_t)row * CAP;

    int j = 0;
    for (; j + 15 < n; j += 16) {
        int4 ia = *(const int4*)&cp[j];
        int4 ib = *(const int4*)&cp[j + 4];
        int4 ic = *(const int4*)&cp[j + 8];
        int4 id = *(const int4*)&cp[j + 12];
        uint2 u0 = *(const uint2*)(base + (size_t)ia.x * F);
        uint2 u1 = *(const uint2*)(base + (size_t)ia.y * F);
        uint2 u2 = *(const uint2*)(base + (size_t)ia.z * F);
        uint2 u3 = *(const uint2*)(base + (size_t)ia.w * F);
        uint2 u4 = *(const uint2*)(base + (size_t)ib.x * F);
        uint2 u5 = *(const uint2*)(base + (size_t)ib.y * F);
        uint2 u6 = *(const uint2*)(base + (size_t)ib.z * F);
        uint2 u7 = *(const uint2*)(base + (size_t)ib.w * F);
        uint2 u8 = *(const uint2*)(base + (size_t)ic.x * F);
        uint2 u9 = *(const uint2*)(base + (size_t)ic.y * F);
        uint2 uA = *(const uint2*)(base + (size_t)ic.z * F);
        uint2 uB = *(const uint2*)(base + (size_t)ic.w * F);
        uint2 uC = *(const uint2*)(base + (size_t)id.x * F);
        uint2 uD = *(const uint2*)(base + (size_t)id.y * F);
        uint2 uE = *(const uint2*)(base + (size_t)id.z * F);
        uint2 uF = *(const uint2*)(base + (size_t)id.w * F);
        __half2 x0 = __hadd2(H2REF(u0.x), H2REF(u1.x));
        __half2 x1 = __hadd2(H2REF(u2.x), H2REF(u3.x));
        __half2 x2 = __hadd2(H2REF(u4.x), H2REF(u5.x));
        __half2 x3 = __hadd2(H2REF(u6.x), H2REF(u7.x));
        __half2 x4 = __hadd2(H2REF(u8.x), H2REF(u9.x));
        __half2 x5 = __hadd2(H2REF(uA.x), H2REF(uB.x));
        __half2 x6 = __hadd2(H2REF(uC.x), H2REF(uD.x));
        __half2 x7 = __hadd2(H2REF(uE.x), H2REF(uF.x));
        x0 = __hadd2(x0, x1); x2 = __hadd2(x2, x3);
        x4 = __hadd2(x4, x5); x6 = __hadd2(x6, x7);
        x0 = __hadd2(x0, x2); x4 = __hadd2(x4, x6);
        x0 = __hadd2(x0, x4);
        __half2 y0 = __hadd2(H2REF(u0.y), H2REF(u1.y));
        __half2 y1 = __hadd2(H2REF(u2.y), H2REF(u3.y));
        __half2 y2 = __hadd2(H2REF(u4.y), H2REF(u5.y));
        __half2 y3 = __hadd2(H2REF(u6.y), H2REF(u7.y));
        __half2 y4 = __hadd2(H2REF(u8.y), H2REF(u9.y));
        __half2 y5 = __hadd2(H2REF(uA.y), H2REF(uB.y));
        __half2 y6 = __hadd2(H2REF(uC.y), H2REF(uD.y));
        __half2 y7 = __hadd2(H2REF(uE.y), H2REF(uF.y));
        y0 = __hadd2(y0, y1); y2 = __hadd2(y2, y3);
        y4 = __hadd2(y4, y5); y6 = __hadd2(y6, y7);
        y0 = __hadd2(y0, y2); y4 = __hadd2(y4, y6);
        y0 = __hadd2(y0, y4);
        float2 fx = __half22float2(x0);
        float2 fy = __half22float2(y0);
        a0 += fx.x; a1 += fx.y; a2 += fy.x; a3 += fy.y;
    }
    for (; j + 7 < n; j += 8) {
        int4 ia = *(const int4*)&cp[j];
        int4 ib = *(const int4*)&cp[j + 4];
        uint2 u0 = *(const uint2*)(base + (size_t)ia.x * F);
        uint2 u1 = *(const uint2*)(base + (size_t)ia.y * F);
        uint2 u2 = *(const uint2*)(base + (size_t)ia.z * F);
        uint2 u3 = *(const uint2*)(base + (size_t)ia.w * F);
        uint2 u4 = *(const uint2*)(base + (size_t)ib.x * F);
        uint2 u5 = *(const uint2*)(base + (size_t)ib.y * F);
        uint2 u6 = *(const uint2*)(base + (size_t)ib.z * F);
        uint2 u7 = *(const uint2*)(base + (size_t)ib.w * F);
        __half2 x0 = __hadd2(H2REF(u0.x), H2REF(u1.x));
        __half2 x1 = __hadd2(H2REF(u2.x), H2REF(u3.x));
        __half2 x2 = __hadd2(H2REF(u4.x), H2REF(u5.x));
        __half2 x3 = __hadd2(H2REF(u6.x), H2REF(u7.x));
        x0 = __hadd2(x0, x1); x2 = __hadd2(x2, x3);
        x0 = __hadd2(x0, x2);
        __half2 y0 = __hadd2(H2REF(u0.y), H2REF(u1.y));
        __half2 y1 = __hadd2(H2REF(u2.y), H2REF(u3.y));
        __half2 y2 = __hadd2(H2REF(u4.y), H2REF(u5.y));
        __half2 y3 = __hadd2(H2REF(u6.y), H2REF(u7.y));
        y0 = __hadd2(y0, y1); y2 = __hadd2(y2, y3);
        y0 = __hadd2(y0, y2);
        float2 fx = __half22float2(x0);
        float2 fy = __half22float2(y0);
        a0 += fx.x; a1 += fx.y; a2 += fy.x; a3 += fy.y;
    }
    for (; j < n; j++) {
        int c = __ldg(&cp[j]);
        uint2 u = *(const uint2*)(base + (size_t)c * F);
        float2 f;
        f = __half22float2(H2REF(u.x)); a0 += f.x; a1 += f.y;
        f = __half22float2(H2REF(u.y)); a2 += f.x; a3 += f.y;
    }

    a0 = fmaxf(a0 * di, 0.f); a1 = fmaxf(a1 * di, 0.f);
    a2 = fmaxf(a2 * di, 0.f); a3 = fmaxf(a3 * di, 0.f);
    __half2 h0 = __floats2half2_rn(a0, a1);
    __half2 h1 = __floats2half2_rn(a2, a3);
    uint2 u;
    u.x = *(uint32_t*)&h0; u.y = *(uint32_t*)&h1;
    *(uint2*)(Hout + (size_t)row * F + (size_t)lane * 4) = u;
}

// ---------------- SpMM2: out[i] = dinv[i] * (sum_adj z1s[c] + z1s[i]) -------
__global__ void __launch_bounds__(256) spmm_out(const __half* __restrict__ Hs,
                                                float* __restrict__ Hout) {
    constexpr int F = N_CLASSES;
    const int lane = threadIdx.x & 31;
    const int warp = threadIdx.x >> 5;
    const int row  = blockIdx.x * 8 + warp;
    if (row >= N_NODES) return;

    const float di = g_dinv[row];
    const __half* __restrict__ base = Hs + (size_t)lane * 2;

    float a0, a1;
    {
        unsigned int u = *(const unsigned int*)(base + (size_t)row * F);
        float2 f = __half22float2(H2REF(u));
        a0 = f.x; a1 = f.y;
    }
    int n = g_cnt[row];
    n = (n < CAP) ? n : CAP;
    const int* __restrict__ cp = g_cols + (size_t)row * CAP;

    int j = 0;
    for (; j + 15 < n; j += 16) {
        int4 ia = *(const int4*)&cp[j];
        int4 ib = *(const int4*)&cp[j + 4];
        int4 ic = *(const int4*)&cp[j + 8];
        int4 id = *(const int4*)&cp[j + 12];
        unsigned int u0 = *(const unsigned int*)(base + (size_t)ia.x * F);
        unsigned int u1 = *(const unsigned int*)(base + (size_t)ia.y * F);
        unsigned int u2 = *(const unsigned int*)(base + (size_t)ia.z * F);
        unsigned int u3 = *(const unsigned int*)(base + (size_t)ia.w * F);
        unsigned int u4 = *(const unsigned int*)(base + (size_t)ib.x * F);
        unsigned int u5 = *(const unsigned int*)(base + (size_t)ib.y * F);
        unsigned int u6 = *(const unsigned int*)(base + (size_t)ib.z * F);
        unsigned int u7 = *(const unsigned int*)(base + (size_t)ib.w * F);
        unsigned int u8 = *(const unsigned int*)(base + (size_t)ic.x * F);
        unsigned int u9 = *(const unsigned int*)(base + (size_t)ic.y * F);
        unsigned int uA = *(const unsigned int*)(base + (size_t)ic.z * F);
        unsigned int uB = *(const unsigned int*)(base + (size_t)ic.w * F);
        unsigned int uC = *(const unsigned int*)(base + (size_t)id.x * F);
        unsigned int uD = *(const unsigned int*)(base + (size_t)id.y * F);
        unsigned int uE = *(const unsigned int*)(base + (size_t)id.z * F);
        unsigned int uF = *(const unsigned int*)(base + (size_t)id.w * F);
        __half2 s0 = __hadd2(H2REF(u0), H2REF(u1));
        __half2 s1 = __hadd2(H2REF(u2), H2REF(u3));
        __half2 s2 = __hadd2(H2REF(u4), H2REF(u5));
        __half2 s3 = __hadd2(H2REF(u6), H2REF(u7));
        __half2 s4 = __hadd2(H2REF(u8), H2REF(u9));
        __half2 s5 = __hadd2(H2REF(uA), H2REF(uB));
        __half2 s6 = __hadd2(H2REF(uC), H2REF(uD));
        __half2 s7 = __hadd2(H2REF(uE), H2REF(uF));
        s0 = __hadd2(s0, s1); s2 = __hadd2(s2, s3);
        s4 = __hadd2(s4, s5); s6 = __hadd2(s6, s7);
        s0 = __hadd2(s0, s2); s4 = __hadd2(s4, s6);
        s0 = __hadd2(s0, s4);
        float2 f = __half22float2(s0);
        a0 += f.x; a1 += f.y;
    }
    for (; j + 7 < n; j += 8) {
        int4 ia = *(const int4*)&cp[j];
        int4 ib = *(const int4*)&cp[j + 4];
        unsigned int u0 = *(const unsigned int*)(base + (size_t)ia.x * F);
        unsigned int u1 = *(const unsigned int*)(base + (size_t)ia.y * F);
        unsigned int u2 = *(const unsigned int*)(base + (size_t)ia.z * F);
        unsigned int u3 = *(const unsigned int*)(base + (size_t)ia.w * F);
        unsigned int u4 = *(const unsigned int*)(base + (size_t)ib.x * F);
        unsigned int u5 = *(const unsigned int*)(base + (size_t)ib.y * F);
        unsigned int u6 = *(const unsigned int*)(base + (size_t)ib.z * F);
        unsigned int u7 = *(const unsigned int*)(base + (size_t)ib.w * F);
        __half2 s0 = __hadd2(H2REF(u0), H2REF(u1));
        __half2 s1 = __hadd2(H2REF(u2), H2REF(u3));
        __half2 s2 = __hadd2(H2REF(u4), H2REF(u5));
        __half2 s3 = __hadd2(H2REF(u6), H2REF(u7));
        s0 = __hadd2(s0, s1); s2 = __hadd2(s2, s3);
        s0 = __hadd2(s0, s2);
        float2 f = __half22float2(s0);
        a0 += f.x; a1 += f.y;
    }
    for (; j < n; j++) {
        int c = __ldg(&cp[j]);
        unsigned int u = *(const unsigned int*)(base + (size_t)c * F);
        float2 f = __half22float2(H2REF(u));
        a0 += f.x; a1 += f.y;
    }

    a0 *= di; a1 *= di;
    *(float2*)&Hout[(size_t)row * F + (size_t)lane * 2] = make_float2(a0, a1);
}

// ---------------- launch ----------------------------------------------------
extern "C" void kernel_launch(void* const* d_in, const int* in_sizes, int n_in,
                              void* d_out, int out_size) {
    const float* x  = (const float*)d_in[0];
    const float* W0 = (const float*)d_in[1];
    const float* W1 = (const float*)d_in[2];
    const int*   ei = (const int*)d_in[3];
    float* out = (float*)d_out;

    __half* z0sp; __half* hhp; __half* z1sp; int* cntp; __half* wt0p; __half* wt1p;
    cudaGetSymbolAddress((void**)&z0sp, g_z0s);
    cudaGetSymbolAddress((void**)&hhp,  g_hh);
    cudaGetSymbolAddress((void**)&z1sp, g_z1s);
    cudaGetSymbolAddress((void**)&cntp, g_cnt);
    cudaGetSymbolAddress((void**)&wt0p, g_WT0);
    cudaGetSymbolAddress((void**)&wt1p, g_WT1);

    const int SMEM1 = 128 * 136 * 2 + 128 * 136 * 2;   // 69632
    const int SMEM2 = 128 * 136 * 2 + 64 * 136 * 2;    // 52224
    cudaFuncSetAttribute(gemm_mma,   cudaFuncAttributeMaxDynamicSharedMemorySize, SMEM1);
    cudaFuncSetAttribute(gemm_mma_h, cudaFuncAttributeMaxDynamicSharedMemorySize, SMEM2);

    const int T = 256;
    const int NBLK = (N_NODES + 127) / 128;   // 391

    cudaMemsetAsync(cntp, 0, N_NODES * sizeof(int));
    k_fill<<<((N_EDGES + 1) / 2 + T - 1) / T, T>>>(ei);
    k_prep<<<(N_NODES + T - 1) / T, T>>>(W0, W1);

    // z0s = dinv * (x @ W0) -> fp16
    gemm_mma<<<NBLK, 256, SMEM1>>>(N_NODES, x, wt0p, z0sp);

    // h = relu(dinv * gather(z0s)) -> fp16
    spmm_h16<<<(N_NODES + 7) / 8, 256>>>(z0sp, hhp);

    // z1s = dinv * (h @ W1) -> fp16
    gemm_mma_h<<<NBLK, 256, SMEM2>>>(N_NODES, hhp, wt1p, z1sp);

    // out = dinv * gather(z1s) -> fp32
    spmm_out<<<(N_NODES + 7) / 8, 256>>>(z1sp, out);
}

// round 17
// speedup vs baseline: 1.0824x; 1.0430x over previous
#include <cuda_runtime.h>
#include <cuda_fp16.h>
#include <math.h>
#include <cstdint>

#define N_NODES   50000
#define N_EDGES   800000
#define D_FEAT    128
#define D_HID     128
#define N_CLASSES 64
#define CAP       96

#define H2REF(u) (*(__half2*)&(u))

// PDL: wait for the predecessor grid (launched with programmatic stream
// serialization) before consuming its output. Plain sm_90+ PTX.
__device__ __forceinline__ void grid_dep_wait() {
    asm volatile("griddepcontrol.wait;" ::: "memory");
}

// ---------------- scratch (device globals; no allocation allowed) ----------
__device__ int    g_cnt[N_NODES];
__device__ float  g_dinv[N_NODES];
__device__ int    g_cols[(size_t)N_NODES * CAP];
__device__ __half g_z0s[(size_t)N_NODES * D_HID];
__device__ __half g_hh [(size_t)N_NODES * D_HID];
__device__ __half g_z1s[(size_t)N_NODES * N_CLASSES];
__device__ __half g_WT0[D_HID * D_FEAT];
__device__ __half g_WT1[N_CLASSES * D_HID];

// ---------------- helpers ----------------------------------------------------
__device__ __forceinline__ uint32_t smem_u32(const void* p) {
    uint32_t a;
    asm("{ .reg .u64 t; cvta.to.shared.u64 t, %1; cvt.u32.u64 %0, t; }" : "=r"(a) : "l"(p));
    return a;
}
__device__ __forceinline__ void ldsm_x4(uint32_t& r0, uint32_t& r1, uint32_t& r2, uint32_t& r3,
                                        uint32_t addr) {
    asm volatile("ldmatrix.sync.aligned.m8n8.x4.shared.b16 {%0,%1,%2,%3}, [%4];"
                 : "=r"(r0), "=r"(r1), "=r"(r2), "=r"(r3) : "r"(addr));
}
__device__ __forceinline__ void ldsm_x2(uint32_t& r0, uint32_t& r1, uint32_t addr) {
    asm volatile("ldmatrix.sync.aligned.m8n8.x2.shared.b16 {%0,%1}, [%2];"
                 : "=r"(r0), "=r"(r1) : "r"(addr));
}
__device__ __forceinline__ void mma16816(float* d, uint32_t a0, uint32_t a1, uint32_t a2,
                                         uint32_t a3, uint32_t b0, uint32_t b1) {
    asm volatile(
        "mma.sync.aligned.m16n8k16.row.col.f32.f16.f16.f32 "
        "{%0,%1,%2,%3}, {%4,%5,%6,%7}, {%8,%9}, {%0,%1,%2,%3};"
        : "+f"(d[0]), "+f"(d[1]), "+f"(d[2]), "+f"(d[3])
        : "r"(a0), "r"(a1), "r"(a2), "r"(a3), "r"(b0), "r"(b1));
}

// ---------------- adjacency build ------------------------------------------
__global__ void k_fill(const int* __restrict__ ei) {
    int e = blockIdx.x * blockDim.x + threadIdx.x;
    if (e < N_EDGES) {
        int s = ei[e];
        int d = ei[N_EDGES + e];
        int ps = atomicAdd(&g_cnt[s], 1);
        if (ps < CAP) g_cols[(size_t)s * CAP + ps] = d;
        int pd = atomicAdd(&g_cnt[d], 1);
        if (pd < CAP) g_cols[(size_t)d * CAP + pd] = s;
    }
}

// ---------------- dinv + W transpose + fp16 convert (fused) -----------------
__global__ void k_prep(const float* __restrict__ W0, const float* __restrict__ W1) {
    grid_dep_wait();
    int i = blockIdx.x * blockDim.x + threadIdx.x;
    if (i < N_NODES) g_dinv[i] = rsqrtf((float)(g_cnt[i] + 1));
    if (i < D_HID * D_FEAT) {
        int n = i / D_FEAT, k = i % D_FEAT;
        g_WT0[i] = __float2half_rn(W0[(size_t)k * D_HID + n]);
    }
    if (i < N_CLASSES * D_HID) {
        int n = i / D_HID, k = i % D_HID;
        g_WT1[i] = __float2half_rn(W1[(size_t)k * N_CLASSES + n]);
    }
}

// ---------------- GEMM1 (HMMA, BM=128): z0s = dinv * (x @ W0) ---------------
__global__ void __launch_bounds__(256) gemm_mma(int M, const float* __restrict__ A,
                                                const __half* __restrict__ WT,
                                                __half* __restrict__ C) {
    constexpr int NOUT = 128;
    constexpr int PAD  = 136;
    constexpr int NT   = NOUT / 8;
    constexpr int A_SZ = 128 * PAD * 2;

    extern __shared__ char smem[];
    const uint32_t sbase = smem_u32(smem);
    const uint32_t OFF_A = 0, OFF_B = A_SZ;

    const int tid = threadIdx.x;
    const int w   = tid >> 5;
    const int l   = tid & 31;
    const int blockRow = blockIdx.x * 128;

    grid_dep_wait();

#pragma unroll
    for (int p = 0; p < 16; p++) {
        const int row  = w + 8 * p;
        const int grow = blockRow + row;
        float4 v = make_float4(0.f, 0.f, 0.f, 0.f);
        if (grow < M) v = ((const float4*)A)[(size_t)grow * 32 + l];
        __half2 h0 = __floats2half2_rn(v.x, v.y);
        __half2 h1 = __floats2half2_rn(v.z, v.w);
        uint2 u;
        u.x = *(uint32_t*)&h0; u.y = *(uint32_t*)&h1;
        *(uint2*)((__half*)(smem + OFF_A) + row * PAD + l * 4) = u;
    }
    for (int i = tid; i < NOUT * 16; i += 256) {
        int row = i >> 4, c8 = (i & 15) * 8;
        uint4 u = *(const uint4*)&WT[(size_t)row * 128 + c8];
        *(uint4*)((__half*)(smem + OFF_B) + row * PAD + c8) = u;
    }
    __syncthreads();

    float acc[NT][4];
#pragma unroll
    for (int nt = 0; nt < NT; nt++)
#pragma unroll
        for (int j = 0; j < 4; j++) acc[nt][j] = 0.f;

    const uint32_t a_lane = sbase + OFF_A +
        (uint32_t)(((w * 16) + (l & 15)) * PAD + ((l & 16) ? 8 : 0)) * 2;
    const uint32_t b_lane = sbase + OFF_B +
        (uint32_t)((l & 7) * PAD + ((l >> 3) & 1) * 8) * 2;

#pragma unroll
    for (int kt = 0; kt < 8; kt++) {
        uint32_t a0, a1, a2, a3;
        ldsm_x4(a0, a1, a2, a3, a_lane + kt * 32);
#pragma unroll
        for (int nt = 0; nt < NT; nt++) {
            uint32_t b0, b1;
            ldsm_x2(b0, b1, b_lane + (uint32_t)(nt * 8 * PAD + kt * 16) * 2);
            mma16816(acc[nt], a0, a1, a2, a3, b0, b1);
        }
    }

    __syncthreads();
    __half* Cs = (__half*)(smem + OFF_A);
    {
        const int r0l = w * 16 + (l >> 2);
        const int r1l = r0l + 8;
        const int g0 = blockRow + r0l, g1r = blockRow + r1l;
        const float s0 = (g0 < M) ? g_dinv[g0] : 0.f;
        const float s1 = (g1r < M) ? g_dinv[g1r] : 0.f;
        const int col = (l & 3) * 2;
#pragma unroll
        for (int nt = 0; nt < NT; nt++) {
            __half2 h0 = __floats2half2_rn(s0 * acc[nt][0], s0 * acc[nt][1]);
            __half2 h1 = __floats2half2_rn(s1 * acc[nt][2], s1 * acc[nt][3]);
            *(__half2*)&Cs[r0l * PAD + nt * 8 + col] = h0;
            *(__half2*)&Cs[r1l * PAD + nt * 8 + col] = h1;
        }
    }
    __syncthreads();
#pragma unroll
    for (int p = 0; p < 8; p++) {
        const int rl   = w * 16 + p * 2 + (l >> 4);
        const int grow = blockRow + rl;
        if (grow < M) {
            uint4 v = *(uint4*)&Cs[rl * PAD + (l & 15) * 8];
            *(uint4*)&C[(size_t)grow * NOUT + (l & 15) * 8] = v;
        }
    }
}

// ---------------- GEMM2 (HMMA, BM=128): z1s = dinv * (h @ W1), A fp16 --------
__global__ void __launch_bounds__(256) gemm_mma_h(int M, const __half* __restrict__ A,
                                                  const __half* __restrict__ WT,
                                                  __half* __restrict__ C) {
    constexpr int NOUT = 64;
    constexpr int PAD  = 136;
    constexpr int NT   = NOUT / 8;
    constexpr int A_SZ = 128 * PAD * 2;

    extern __shared__ char smem[];
    const uint32_t sbase = smem_u32(smem);
    const uint32_t OFF_A = 0, OFF_B = A_SZ;

    const int tid = threadIdx.x;
    const int w   = tid >> 5;
    const int l   = tid & 31;
    const int blockRow = blockIdx.x * 128;

    grid_dep_wait();

#pragma unroll
    for (int p = 0; p < 16; p++) {
        const int row  = w + 8 * p;
        const int grow = blockRow + row;
        uint2 u = make_uint2(0, 0);
        if (grow < M) u = ((const uint2*)A)[(size_t)grow * 32 + l];
        *(uint2*)((__half*)(smem + OFF_A) + row * PAD + l * 4) = u;
    }
    for (int i = tid; i < NOUT * 16; i += 256) {
        int row = i >> 4, c8 = (i & 15) * 8;
        uint4 u = *(const uint4*)&WT[(size_t)row * 128 + c8];
        *(uint4*)((__half*)(smem + OFF_B) + row * PAD + c8) = u;
    }
    __syncthreads();

    float acc[NT][4];
#pragma unroll
    for (int nt = 0; nt < NT; nt++)
#pragma unroll
        for (int j = 0; j < 4; j++) acc[nt][j] = 0.f;

    const uint32_t a_lane = sbase + OFF_A +
        (uint32_t)(((w * 16) + (l & 15)) * PAD + ((l & 16) ? 8 : 0)) * 2;
    const uint32_t b_lane = sbase + OFF_B +
        (uint32_t)((l & 7) * PAD + ((l >> 3) & 1) * 8) * 2;

#pragma unroll
    for (int kt = 0; kt < 8; kt++) {
        uint32_t a0, a1, a2, a3;
        ldsm_x4(a0, a1, a2, a3, a_lane + kt * 32);
#pragma unroll
        for (int nt = 0; nt < NT; nt++) {
            uint32_t b0, b1;
            ldsm_x2(b0, b1, b_lane + (uint32_t)(nt * 8 * PAD + kt * 16) * 2);
            mma16816(acc[nt], a0, a1, a2, a3, b0, b1);
        }
    }

    __syncthreads();
    __half* Cs = (__half*)(smem + OFF_A);
    {
        const int r0l = w * 16 + (l >> 2);
        const int r1l = r0l + 8;
        const int g0 = blockRow + r0l, g1r = blockRow + r1l;
        const float s0 = (g0 < M) ? g_dinv[g0] : 0.f;
        const float s1 = (g1r < M) ? g_dinv[g1r] : 0.f;
        const int col = (l & 3) * 2;
#pragma unroll
        for (int nt = 0; nt < NT; nt++) {
            __half2 h0 = __floats2half2_rn(s0 * acc[nt][0], s0 * acc[nt][1]);
            __half2 h1 = __floats2half2_rn(s1 * acc[nt][2], s1 * acc[nt][3]);
            *(__half2*)&Cs[r0l * PAD + nt * 8 + col] = h0;
            *(__half2*)&Cs[r1l * PAD + nt * 8 + col] = h1;
        }
    }
    __syncthreads();
#pragma unroll
    for (int p = 0; p < 4; p++) {
        const int rl   = w * 16 + p * 4 + (l >> 3);
        const int grow = blockRow + rl;
        if (grow < M) {
            uint4 v = *(uint4*)&Cs[rl * PAD + (l & 7) * 8];
            *(uint4*)&C[(size_t)grow * NOUT + (l & 7) * 8] = v;
        }
    }
}

// ---------------- SpMM1: h = relu(dinv * (gather z0s)) -> fp16 --------------
__global__ void __launch_bounds__(256) spmm_h16(const __half* __restrict__ Hs,
                                                __half* __restrict__ Hout) {
    constexpr int F = D_HID;
    const int lane = threadIdx.x & 31;
    const int warp = threadIdx.x >> 5;
    const int row  = blockIdx.x * 8 + warp;
    grid_dep_wait();
    if (row >= N_NODES) return;

    const float di = g_dinv[row];
    const __half* __restrict__ base = Hs + (size_t)lane * 4;

    float a0, a1, a2, a3;
    {
        uint2 u = *(const uint2*)(base + (size_t)row * F);
        float2 f01 = __half22float2(H2REF(u.x));
        float2 f23 = __half22float2(H2REF(u.y));
        a0 = f01.x; a1 = f01.y; a2 = f23.x; a3 = f23.y;
    }

    int n = g_cnt[row];
    n = (n < CAP) ? n : CAP;
    const int* __restrict__ cp = g_cols + (size_t)row * CAP;

    int j = 0;
    for (; j + 15 < n; j += 16) {
        int4 ia = *(const int4*)&cp[j];
        int4 ib = *(const int4*)&cp[j + 4];
        int4 ic = *(const int4*)&cp[j + 8];
        int4 id = *(const int4*)&cp[j + 12];
        uint2 u0 = *(const uint2*)(base + (size_t)ia.x * F);
        uint2 u1 = *(const uint2*)(base + (size_t)ia.y * F);
        uint2 u2 = *(const uint2*)(base + (size_t)ia.z * F);
        uint2 u3 = *(const uint2*)(base + (size_t)ia.w * F);
        uint2 u4 = *(const uint2*)(base + (size_t)ib.x * F);
        uint2 u5 = *(const uint2*)(base + (size_t)ib.y * F);
        uint2 u6 = *(const uint2*)(base + (size_t)ib.z * F);
        uint2 u7 = *(const uint2*)(base + (size_t)ib.w * F);
        uint2 u8 = *(const uint2*)(base + (size_t)ic.x * F);
        uint2 u9 = *(const uint2*)(base + (size_t)ic.y * F);
        uint2 uA = *(const uint2*)(base + (size_t)ic.z * F);
        uint2 uB = *(const uint2*)(base + (size_t)ic.w * F);
        uint2 uC = *(const uint2*)(base + (size_t)id.x * F);
        uint2 uD = *(const uint2*)(base + (size_t)id.y * F);
        uint2 uE = *(const uint2*)(base + (size_t)id.z * F);
        uint2 uF = *(const uint2*)(base + (size_t)id.w * F);
        __half2 x0 = __hadd2(H2REF(u0.x), H2REF(u1.x));
        __half2 x1 = __hadd2(H2REF(u2.x), H2REF(u3.x));
        __half2 x2 = __hadd2(H2REF(u4.x), H2REF(u5.x));
        __half2 x3 = __hadd2(H2REF(u6.x), H2REF(u7.x));
        __half2 x4 = __hadd2(H2REF(u8.x), H2REF(u9.x));
        __half2 x5 = __hadd2(H2REF(uA.x), H2REF(uB.x));
        __half2 x6 = __hadd2(H2REF(uC.x), H2REF(uD.x));
        __half2 x7 = __hadd2(H2REF(uE.x), H2REF(uF.x));
        x0 = __hadd2(x0, x1); x2 = __hadd2(x2, x3);
        x4 = __hadd2(x4, x5); x6 = __hadd2(x6, x7);
        x0 = __hadd2(x0, x2); x4 = __hadd2(x4, x6);
        x0 = __hadd2(x0, x4);
        __half2 y0 = __hadd2(H2REF(u0.y), H2REF(u1.y));
        __half2 y1 = __hadd2(H2REF(u2.y), H2REF(u3.y));
        __half2 y2 = __hadd2(H2REF(u4.y), H2REF(u5.y));
        __half2 y3 = __hadd2(H2REF(u6.y), H2REF(u7.y));
        __half2 y4 = __hadd2(H2REF(u8.y), H2REF(u9.y));
        __half2 y5 = __hadd2(H2REF(uA.y), H2REF(uB.y));
        __half2 y6 = __hadd2(H2REF(uC.y), H2REF(uD.y));
        __half2 y7 = __hadd2(H2REF(uE.y), H2REF(uF.y));
        y0 = __hadd2(y0, y1); y2 = __hadd2(y2, y3);
        y4 = __hadd2(y4, y5); y6 = __hadd2(y6, y7);
        y0 = __hadd2(y0, y2); y4 = __hadd2(y4, y6);
        y0 = __hadd2(y0, y4);
        float2 fx = __half22float2(x0);
        float2 fy = __half22float2(y0);
        a0 += fx.x; a1 += fx.y; a2 += fy.x; a3 += fy.y;
    }
    for (; j + 7 < n; j += 8) {
        int4 ia = *(const int4*)&cp[j];
        int4 ib = *(const int4*)&cp[j + 4];
        uint2 u0 = *(const uint2*)(base + (size_t)ia.x * F);
        uint2 u1 = *(const uint2*)(base + (size_t)ia.y * F);
        uint2 u2 = *(const uint2*)(base + (size_t)ia.z * F);
        uint2 u3 = *(const uint2*)(base + (size_t)ia.w * F);
        uint2 u4 = *(const uint2*)(base + (size_t)ib.x * F);
        uint2 u5 = *(const uint2*)(base + (size_t)ib.y * F);
        uint2 u6 = *(const uint2*)(base + (size_t)ib.z * F);
        uint2 u7 = *(const uint2*)(base + (size_t)ib.w * F);
        __half2 x0 = __hadd2(H2REF(u0.x), H2REF(u1.x));
        __half2 x1 = __hadd2(H2REF(u2.x), H2REF(u3.x));
        __half2 x2 = __hadd2(H2REF(u4.x), H2REF(u5.x));
        __half2 x3 = __hadd2(H2REF(u6.x), H2REF(u7.x));
        x0 = __hadd2(x0, x1); x2 = __hadd2(x2, x3);
        x0 = __hadd2(x0, x2);
        __half2 y0 = __hadd2(H2REF(u0.y), H2REF(u1.y));
        __half2 y1 = __hadd2(H2REF(u2.y), H2REF(u3.y));
        __half2 y2 = __hadd2(H2REF(u4.y), H2REF(u5.y));
        __half2 y3 = __hadd2(H2REF(u6.y), H2REF(u7.y));
        y0 = __hadd2(y0, y1); y2 = __hadd2(y2, y3);
        y0 = __hadd2(y0, y2);
        float2 fx = __half22float2(x0);
        float2 fy = __half22float2(y0);
        a0 += fx.x; a1 += fx.y; a2 += fy.x; a3 += fy.y;
    }
    for (; j < n; j++) {
        int c = __ldg(&cp[j]);
        uint2 u = *(const uint2*)(base + (size_t)c * F);
        float2 f;
        f = __half22float2(H2REF(u.x)); a0 += f.x; a1 += f.y;
        f = __half22float2(H2REF(u.y)); a2 += f.x; a3 += f.y;
    }

    a0 = fmaxf(a0 * di, 0.f); a1 = fmaxf(a1 * di, 0.f);
    a2 = fmaxf(a2 * di, 0.f); a3 = fmaxf(a3 * di, 0.f);
    __half2 h0 = __floats2half2_rn(a0, a1);
    __half2 h1 = __floats2half2_rn(a2, a3);
    uint2 u;
    u.x = *(uint32_t*)&h0; u.y = *(uint32_t*)&h1;
    *(uint2*)(Hout + (size_t)row * F + (size_t)lane * 4) = u;
}

// ---------------- SpMM2: out[i] = dinv[i] * (sum_adj z1s[c] + z1s[i]) -------
__global__ void __launch_bounds__(256) spmm_out(const __half* __restrict__ Hs,
                                                float* __restrict__ Hout) {
    constexpr int F = N_CLASSES;
    const int lane = threadIdx.x & 31;
    const int warp = threadIdx.x >> 5;
    const int row  = blockIdx.x * 8 + warp;
    grid_dep_wait();
    if (row >= N_NODES) return;

    const float di = g_dinv[row];
    const __half* __restrict__ base = Hs + (size_t)lane * 2;

    float a0, a1;
    {
        unsigned int u = *(const unsigned int*)(base + (size_t)row * F);
        float2 f = __half22float2(H2REF(u));
        a0 = f.x; a1 = f.y;
    }
    int n = g_cnt[row];
    n = (n < CAP) ? n : CAP;
    const int* __restrict__ cp = g_cols + (size_t)row * CAP;

    int j = 0;
    for (; j + 15 < n; j += 16) {
        int4 ia = *(const int4*)&cp[j];
        int4 ib = *(const int4*)&cp[j + 4];
        int4 ic = *(const int4*)&cp[j + 8];
        int4 id = *(const int4*)&cp[j + 12];
        unsigned int u0 = *(const unsigned int*)(base + (size_t)ia.x * F);
        unsigned int u1 = *(const unsigned int*)(base + (size_t)ia.y * F);
        unsigned int u2 = *(const unsigned int*)(base + (size_t)ia.z * F);
        unsigned int u3 = *(const unsigned int*)(base + (size_t)ia.w * F);
        unsigned int u4 = *(const unsigned int*)(base + (size_t)ib.x * F);
        unsigned int u5 = *(const unsigned int*)(base + (size_t)ib.y * F);
        unsigned int u6 = *(const unsigned int*)(base + (size_t)ib.z * F);
        unsigned int u7 = *(const unsigned int*)(base + (size_t)ib.w * F);
        unsigned int u8 = *(const unsigned int*)(base + (size_t)ic.x * F);
        unsigned int u9 = *(const unsigned int*)(base + (size_t)ic.y * F);
        unsigned int uA = *(const unsigned int*)(base + (size_t)ic.z * F);
        unsigned int uB = *(const unsigned int*)(base + (size_t)ic.w * F);
        unsigned int uC = *(const unsigned int*)(base + (size_t)id.x * F);
        unsigned int uD = *(const unsigned int*)(base + (size_t)id.y * F);
        unsigned int uE = *(const unsigned int*)(base + (size_t)id.z * F);
        unsigned int uF = *(const unsigned int*)(base + (size_t)id.w * F);
        __half2 s0 = __hadd2(H2REF(u0), H2REF(u1));
        __half2 s1 = __hadd2(H2REF(u2), H2REF(u3));
        __half2 s2 = __hadd2(H2REF(u4), H2REF(u5));
        __half2 s3 = __hadd2(H2REF(u6), H2REF(u7));
        __half2 s4 = __hadd2(H2REF(u8), H2REF(u9));
        __half2 s5 = __hadd2(H2REF(uA), H2REF(uB));
        __half2 s6 = __hadd2(H2REF(uC), H2REF(uD));
        __half2 s7 = __hadd2(H2REF(uE), H2REF(uF));
        s0 = __hadd2(s0, s1); s2 = __hadd2(s2, s3);
        s4 = __hadd2(s4, s5); s6 = __hadd2(s6, s7);
        s0 = __hadd2(s0, s2); s4 = __hadd2(s4, s6);
        s0 = __hadd2(s0, s4);
        float2 f = __half22float2(s0);
        a0 += f.x; a1 += f.y;
    }
    for (; j + 7 < n; j += 8) {
        int4 ia = *(const int4*)&cp[j];
        int4 ib = *(const int4*)&cp[j + 4];
        unsigned int u0 = *(const unsigned int*)(base + (size_t)ia.x * F);
        unsigned int u1 = *(const unsigned int*)(base + (size_t)ia.y * F);
        unsigned int u2 = *(const unsigned int*)(base + (size_t)ia.z * F);
        unsigned int u3 = *(const unsigned int*)(base + (size_t)ia.w * F);
        unsigned int u4 = *(const unsigned int*)(base + (size_t)ib.x * F);
        unsigned int u5 = *(const unsigned int*)(base + (size_t)ib.y * F);
        unsigned int u6 = *(const unsigned int*)(base + (size_t)ib.z * F);
        unsigned int u7 = *(const unsigned int*)(base + (size_t)ib.w * F);
        __half2 s0 = __hadd2(H2REF(u0), H2REF(u1));
        __half2 s1 = __hadd2(H2REF(u2), H2REF(u3));
        __half2 s2 = __hadd2(H2REF(u4), H2REF(u5));
        __half2 s3 = __hadd2(H2REF(u6), H2REF(u7));
        s0 = __hadd2(s0, s1); s2 = __hadd2(s2, s3);
        s0 = __hadd2(s0, s2);
        float2 f = __half22float2(s0);
        a0 += f.x; a1 += f.y;
    }
    for (; j < n; j++) {
        int c = __ldg(&cp[j]);
        unsigned int u = *(const unsigned int*)(base + (size_t)c * F);
        float2 f = __half22float2(H2REF(u));
        a0 += f.x; a1 += f.y;
    }

    a0 *= di; a1 *= di;
    *(float2*)&Hout[(size_t)row * F + (size_t)lane * 2] = make_float2(a0, a1);
}

// ---------------- launch (PDL chain) -----------------------------------------
template <typename... Args>
static inline void launch_pdl(void (*kern)(Args...), dim3 grid, dim3 block,
                              size_t smem, Args... args) {
    cudaLaunchAttribute attr[1];
    attr[0].id = cudaLaunchAttributeProgrammaticStreamSerialization;
    attr[0].val.programmaticStreamSerializationAllowed = 1;
    cudaLaunchConfig_t cfg{};
    cfg.gridDim = grid;
    cfg.blockDim = block;
    cfg.dynamicSmemBytes = smem;
    cfg.stream = 0;
    cfg.attrs = attr;
    cfg.numAttrs = 1;
    cudaLaunchKernelEx(&cfg, kern, args...);
}

extern "C" void kernel_launch(void* const* d_in, const int* in_sizes, int n_in,
                              void* d_out, int out_size) {
    const float* x  = (const float*)d_in[0];
    const float* W0 = (const float*)d_in[1];
    const float* W1 = (const float*)d_in[2];
    const int*   ei = (const int*)d_in[3];
    float* out = (float*)d_out;

    __half* z0sp; __half* hhp; __half* z1sp; int* cntp; __half* wt0p; __half* wt1p;
    cudaGetSymbolAddress((void**)&z0sp, g_z0s);
    cudaGetSymbolAddress((void**)&hhp,  g_hh);
    cudaGetSymbolAddress((void**)&z1sp, g_z1s);
    cudaGetSymbolAddress((void**)&cntp, g_cnt);
    cudaGetSymbolAddress((void**)&wt0p, g_WT0);
    cudaGetSymbolAddress((void**)&wt1p, g_WT1);

    const int SMEM1 = 128 * 136 * 2 + 128 * 136 * 2;   // 69632
    const int SMEM2 = 128 * 136 * 2 + 64 * 136 * 2;    // 52224
    cudaFuncSetAttribute(gemm_mma,   cudaFuncAttributeMaxDynamicSharedMemorySize, SMEM1);
    cudaFuncSetAttribute(gemm_mma_h, cudaFuncAttributeMaxDynamicSharedMemorySize, SMEM2);

    const int T = 256;
    const int NBLK = (N_NODES + 127) / 128;   // 391

    cudaMemsetAsync(cntp, 0, N_NODES * sizeof(int));
    k_fill<<<(N_EDGES + T - 1) / T, T>>>(ei);

    // PDL chain: each kernel's launch/prologue overlaps its predecessor's tail.
    launch_pdl(k_prep, dim3((N_NODES + T - 1) / T), dim3(T), (size_t)0, W0, W1);
    launch_pdl(gemm_mma, dim3(NBLK), dim3(256), (size_t)SMEM1,
               (int)N_NODES, x, (const __half*)wt0p, z0sp);
    launch_pdl(spmm_h16, dim3((N_NODES + 7) / 8), dim3(256), (size_t)0,
               (const __half*)z0sp, hhp);
    launch_pdl(gemm_mma_h, dim3(NBLK), dim3(256), (size_t)SMEM2,
               (int)N_NODES, (const __half*)hhp, (const __half*)wt1p, z1sp);
    launch_pdl(spmm_out, dim3((N_NODES + 7) / 8), dim3(256), (size_t)0,
               (const __half*)z1sp, out);
}